// round 8
// baseline (speedup 1.0000x reference)
#include <cuda_runtime.h>
#include <cuda_bf16.h>
#include <cstdint>

// EdgeModel: out[e] = relu(concat(src,dest,ea,u[batch[e]]) @ W1 + b1) @ W2 + b2
// E=8e6, W1 [4,10], W2 [10,19]. HBM-streaming problem.
// R5: 4 edges/thread strided (amortized weight LDS), conflict-free stride-19
//     STS staging, float4 copy-out. 166us, L1 58% / DRAM 52%.
// R7: copy-out loop -> single cp.async.bulk (TMA) shared->global per block.
//     Removes the staged-read L1 traffic + copy-loop issue pressure.

#define TPB 128
#define EPT 4
#define EPB (TPB * EPT)          // 512 edges per block
#define H1 10
#define H2 19
#define STAGE_FLOATS (EPB * H2)  // 9728 floats = 38912 B (divisible by 16)

__device__ __forceinline__ uint32_t smem_u32(const void* p) {
    uint32_t a;
    asm("{ .reg .u64 t; cvta.to.shared.u64 t, %1; cvt.u32.u64 %0, t; }"
        : "=r"(a) : "l"(p));
    return a;
}

__global__ __launch_bounds__(TPB) void edge_model_kernel(
    const float* __restrict__ src,
    const float* __restrict__ dest,
    const float* __restrict__ ea,
    const float* __restrict__ u,
    const int*   __restrict__ batch,   // int32 on device
    const float* __restrict__ W1,      // [4,10] row-major
    const float* __restrict__ b1,      // [10]
    const float* __restrict__ W2,      // [10,19] row-major
    const float* __restrict__ b2,      // [19]
    float* __restrict__ out,           // [E,19]
    int E)
{
    __shared__ __align__(16) float stage[STAGE_FLOATS];
    __shared__ float sW1[4 * H1];
    __shared__ float sb1[H1];
    __shared__ __align__(16) float sW2p[H1 * 20];  // padded rows: [10][20]
    __shared__ __align__(16) float sb2p[20];

    const int t = threadIdx.x;

    // Weight load: W2 padded to 20-wide rows so &sW2p[j*20 + 4m] is 16B-aligned.
    for (int i = t; i < 4 * H1; i += TPB) sW1[i] = W1[i];
    if (t < H1) sb1[t] = b1[t];
    for (int i = t; i < H1 * 20; i += TPB) {
        int j = i / 20, n = i % 20;
        sW2p[i] = (n < H2) ? W2[j * H2 + n] : 0.0f;
    }
    if (t < 20) sb2p[t] = (t < H2) ? b2[t] : 0.0f;
    __syncthreads();

    const long long base = (long long)blockIdx.x * EPB;
    const int nvalid = (int)min((long long)EPB, (long long)E - base);

    if (nvalid == EPB) {
        // ---- full-block fast path: 4 edges per thread, strided by TPB ----
        float s[EPT], d[EPT], a[EPT], ub[EPT];
        #pragma unroll
        for (int k = 0; k < EPT; k++) {
            const long long e = base + t + k * TPB;
            s[k]  = __ldg(&src[e]);
            d[k]  = __ldg(&dest[e]);
            a[k]  = __ldg(&ea[e]);
            ub[k] = __ldg(&u[__ldg(&batch[e])]);
        }

        // Layer 1: each weight LDS feeds 4 edges' FMAs.
        float h[EPT][H1];
        #pragma unroll
        for (int j = 0; j < H1; j++) {
            const float w0 = sW1[0 * H1 + j];
            const float w1 = sW1[1 * H1 + j];
            const float w2 = sW1[2 * H1 + j];
            const float w3 = sW1[3 * H1 + j];
            const float bb = sb1[j];
            #pragma unroll
            for (int k = 0; k < EPT; k++) {
                float acc = fmaf(ub[k], w3,
                            fmaf(a[k],  w2,
                            fmaf(d[k],  w1,
                            fmaf(s[k],  w0, bb))));
                h[k][j] = fmaxf(acc, 0.0f);
            }
        }

        // Layer 2: n blocked by 4, W2 row chunks via LDS.128.
        #pragma unroll
        for (int n0 = 0; n0 < H2; n0 += 4) {
            const float4 bb4 = *(const float4*)&sb2p[n0];
            float acc[EPT][4];
            #pragma unroll
            for (int k = 0; k < EPT; k++) {
                acc[k][0] = bb4.x; acc[k][1] = bb4.y;
                acc[k][2] = bb4.z; acc[k][3] = bb4.w;
            }
            #pragma unroll
            for (int j = 0; j < H1; j++) {
                const float4 w4 = *(const float4*)&sW2p[j * 20 + n0];
                #pragma unroll
                for (int k = 0; k < EPT; k++) {
                    acc[k][0] = fmaf(h[k][j], w4.x, acc[k][0]);
                    acc[k][1] = fmaf(h[k][j], w4.y, acc[k][1]);
                    acc[k][2] = fmaf(h[k][j], w4.z, acc[k][2]);
                    acc[k][3] = fmaf(h[k][j], w4.w, acc[k][3]);
                }
            }
            // stride-19 STS across lanes: gcd(19,32)=1 -> conflict-free.
            #pragma unroll
            for (int k = 0; k < EPT; k++) {
                float* st = &stage[(k * TPB + t) * H2 + n0];
                #pragma unroll
                for (int m = 0; m < 4; m++)
                    if (n0 + m < H2) st[m] = acc[k][m];
            }
        }
        __syncthreads();

        // ---- bulk async store: TMA drains the stage, no per-thread copy ----
        if (t == 0) {
            // Order the generic-proxy STS writes before the async-proxy read.
            asm volatile("fence.proxy.async.shared::cta;" ::: "memory");
            const uint32_t sptr = smem_u32(stage);
            float* gout = out + base * H2;   // blockIdx * 38912 B, 16B-aligned
            asm volatile(
                "cp.async.bulk.global.shared::cta.bulk_group [%0], [%1], %2;"
                :: "l"(gout), "r"(sptr), "n"(STAGE_FLOATS * 4) : "memory");
            asm volatile("cp.async.bulk.commit_group;" ::: "memory");
            asm volatile("cp.async.bulk.wait_group 0;" ::: "memory");
        }
        __syncthreads();   // keep stage alive until the bulk copy completed
    } else {
        // ---- tail path: scalar per edge + scalar copy-out ----
        for (int k = 0; k < EPT; k++) {
            const int idx = t + k * TPB;
            if (idx >= nvalid) break;
            const long long e = base + idx;
            const float sv = __ldg(&src[e]);
            const float dv = __ldg(&dest[e]);
            const float av = __ldg(&ea[e]);
            const float uv = __ldg(&u[__ldg(&batch[e])]);
            float h[H1];
            #pragma unroll
            for (int j = 0; j < H1; j++) {
                float acc = fmaf(uv, sW1[3 * H1 + j],
                            fmaf(av, sW1[2 * H1 + j],
                            fmaf(dv, sW1[1 * H1 + j],
                            fmaf(sv, sW1[0 * H1 + j], sb1[j]))));
                h[j] = fmaxf(acc, 0.0f);
            }
            #pragma unroll
            for (int n = 0; n < H2; n++) {
                float acc = sb2p[n];
                #pragma unroll
                for (int j = 0; j < H1; j++)
                    acc = fmaf(h[j], sW2p[j * 20 + n], acc);
                stage[idx * H2 + n] = acc;
            }
        }
        __syncthreads();
        float* gout = out + base * H2;
        const int total = nvalid * H2;
        for (int i = t; i < total; i += TPB)
            gout[i] = stage[i];
    }
}

extern "C" void kernel_launch(void* const* d_in, const int* in_sizes, int n_in,
                              void* d_out, int out_size)
{
    const float* src   = (const float*)d_in[0];
    const float* dest  = (const float*)d_in[1];
    const float* ea    = (const float*)d_in[2];
    const float* u     = (const float*)d_in[3];
    const int*   batch = (const int*)d_in[4];
    const float* W1    = (const float*)d_in[5];
    const float* b1    = (const float*)d_in[6];
    const float* W2    = (const float*)d_in[7];
    const float* b2    = (const float*)d_in[8];
    float* out = (float*)d_out;

    const int E = in_sizes[0];
    const int blocks = (E + EPB - 1) / EPB;
    edge_model_kernel<<<blocks, TPB>>>(src, dest, ea, u, batch,
                                       W1, b1, W2, b2, out, E);
}

// round 9
// speedup vs baseline: 1.7907x; 1.7907x over previous
#include <cuda_runtime.h>
#include <cuda_bf16.h>
#include <cstdint>

// EdgeModel: out[e] = relu(concat(src,dest,ea,u[batch[e]]) @ W1 + b1) @ W2 + b2
// E=8e6, W1 [4,10], W2 [10,19]. HBM-streaming problem.
// L1 shared-op rate (~1 op/cyc/SM) is the secondary constraint (R4/R5 fit).
// R8: weights in __constant__ (LDCU uniform port, zero L1 weight traffic),
//     EPT=2 / TPB=128 / 8 blocks per SM for ~50% occupancy,
//     stride-19 STS staging + float4 coalesced copy-out (R7 TMA store was a
//     regression: blocking drain serialized store latency — reverted).

#define TPB 128
#define EPT 2
#define EPB (TPB * EPT)          // 256 edges per block
#define H1 10
#define H2 19
#define STAGE_FLOATS (EPB * H2)  // 4864 floats = 19456 B (divisible by 16)

__constant__ float cW1[4 * H1];   // [4,10] row-major
__constant__ float cb1[H1];
__constant__ float cW2[H1 * H2];  // [10,19] row-major
__constant__ float cb2[H2];

__global__ __launch_bounds__(TPB, 8) void edge_model_kernel(
    const float* __restrict__ src,
    const float* __restrict__ dest,
    const float* __restrict__ ea,
    const float* __restrict__ u,
    const int*   __restrict__ batch,   // int32 on device
    float* __restrict__ out,           // [E,19]
    int E)
{
    __shared__ __align__(16) float stage[STAGE_FLOATS];

    const int t = threadIdx.x;
    const long long base = (long long)blockIdx.x * EPB;
    const int nvalid = (int)min((long long)EPB, (long long)E - base);

    if (nvalid == EPB) {
        // ---- full-block fast path: 2 edges per thread, strided by TPB ----
        float s[EPT], d[EPT], a[EPT], ub[EPT];
        #pragma unroll
        for (int k = 0; k < EPT; k++) {
            const long long e = base + t + k * TPB;
            s[k]  = __ldg(&src[e]);
            d[k]  = __ldg(&dest[e]);
            a[k]  = __ldg(&ea[e]);
            ub[k] = __ldg(&u[__ldg(&batch[e])]);
        }

        // Layer 1: weights via constant/uniform port (no L1 traffic).
        float h[EPT][H1];
        #pragma unroll
        for (int j = 0; j < H1; j++) {
            const float w0 = cW1[0 * H1 + j];
            const float w1 = cW1[1 * H1 + j];
            const float w2 = cW1[2 * H1 + j];
            const float w3 = cW1[3 * H1 + j];
            const float bb = cb1[j];
            #pragma unroll
            for (int k = 0; k < EPT; k++) {
                float acc = fmaf(ub[k], w3,
                            fmaf(a[k],  w2,
                            fmaf(d[k],  w1,
                            fmaf(s[k],  w0, bb))));
                h[k][j] = fmaxf(acc, 0.0f);
            }
        }

        // Layer 2: n blocked by 4; weights from constant memory.
        #pragma unroll
        for (int n0 = 0; n0 < H2; n0 += 4) {
            float acc[EPT][4];
            #pragma unroll
            for (int m = 0; m < 4; m++) {
                const float bv = (n0 + m < H2) ? cb2[n0 + m] : 0.0f;
                #pragma unroll
                for (int k = 0; k < EPT; k++) acc[k][m] = bv;
            }
            #pragma unroll
            for (int j = 0; j < H1; j++) {
                #pragma unroll
                for (int m = 0; m < 4; m++) {
                    if (n0 + m < H2) {
                        const float w = cW2[j * H2 + n0 + m];
                        #pragma unroll
                        for (int k = 0; k < EPT; k++)
                            acc[k][m] = fmaf(h[k][j], w, acc[k][m]);
                    }
                }
            }
            // stride-19 STS across lanes: gcd(19,32)=1 -> conflict-free.
            #pragma unroll
            for (int k = 0; k < EPT; k++) {
                float* st = &stage[(k * TPB + t) * H2 + n0];
                #pragma unroll
                for (int m = 0; m < 4; m++)
                    if (n0 + m < H2) st[m] = acc[k][m];
            }
        }
        __syncthreads();

        // Coalesced float4 copy-out: 4864 floats = 1216 float4.
        // Global base = blockIdx * 19456 B (16B-aligned); stage force-aligned.
        float4* g4 = (float4*)(out + base * H2);
        const float4* s4 = (const float4*)stage;
        #pragma unroll
        for (int i = t; i < STAGE_FLOATS / 4; i += TPB)
            g4[i] = s4[i];
    } else {
        // ---- tail path: scalar per edge + scalar copy-out ----
        for (int k = 0; k < EPT; k++) {
            const int idx = t + k * TPB;
            if (idx >= nvalid) break;
            const long long e = base + idx;
            const float sv = __ldg(&src[e]);
            const float dv = __ldg(&dest[e]);
            const float av = __ldg(&ea[e]);
            const float uv = __ldg(&u[__ldg(&batch[e])]);
            float h[H1];
            #pragma unroll
            for (int j = 0; j < H1; j++) {
                float acc = fmaf(uv, cW1[3 * H1 + j],
                            fmaf(av, cW1[2 * H1 + j],
                            fmaf(dv, cW1[1 * H1 + j],
                            fmaf(sv, cW1[0 * H1 + j], cb1[j]))));
                h[j] = fmaxf(acc, 0.0f);
            }
            #pragma unroll
            for (int n = 0; n < H2; n++) {
                float acc = cb2[n];
                #pragma unroll
                for (int j = 0; j < H1; j++)
                    acc = fmaf(h[j], cW2[j * H2 + n], acc);
                stage[idx * H2 + n] = acc;
            }
        }
        __syncthreads();
        float* gout = out + base * H2;
        const int total = nvalid * H2;
        for (int i = t; i < total; i += TPB)
            gout[i] = stage[i];
    }
}

extern "C" void kernel_launch(void* const* d_in, const int* in_sizes, int n_in,
                              void* d_out, int out_size)
{
    const float* src   = (const float*)d_in[0];
    const float* dest  = (const float*)d_in[1];
    const float* ea    = (const float*)d_in[2];
    const float* u     = (const float*)d_in[3];
    const int*   batch = (const int*)d_in[4];
    float* out = (float*)d_out;

    // Stage weights into constant memory (async D2D memcpys — graph-capturable
    // memcpy nodes, ordered before the kernel node on the same stream).
    cudaMemcpyToSymbolAsync(cW1, d_in[5], 4 * H1 * sizeof(float), 0,
                            cudaMemcpyDeviceToDevice, 0);
    cudaMemcpyToSymbolAsync(cb1, d_in[6], H1 * sizeof(float), 0,
                            cudaMemcpyDeviceToDevice, 0);
    cudaMemcpyToSymbolAsync(cW2, d_in[7], H1 * H2 * sizeof(float), 0,
                            cudaMemcpyDeviceToDevice, 0);
    cudaMemcpyToSymbolAsync(cb2, d_in[8], H2 * sizeof(float), 0,
                            cudaMemcpyDeviceToDevice, 0);

    const int E = in_sizes[0];
    const int blocks = (E + EPB - 1) / EPB;
    edge_model_kernel<<<blocks, TPB>>>(src, dest, ea, u, batch, out, E);
}